// round 15
// baseline (speedup 1.0000x reference)
#include <cuda_runtime.h>
#include <cuda_bf16.h>
#include <math.h>
#include <stdint.h>

#define E_ 8
#define B_ 4096
#define D_ 3072
#define H_ 1024
#define L_ 512
#define C_ 100
typedef __nv_bfloat16 bf16;

// ---------------- device scratch -------------------------------------------
#define WTOTAL 89128960ULL
__device__ __align__(256) bf16 g_whi[WTOTAL];
__device__ __align__(256) bf16 g_wlo[WTOTAL];
__device__ __align__(256) bf16 g_xhi[(size_t)B_ * D_];
__device__ __align__(256) bf16 g_xlo[(size_t)B_ * D_];
__device__ __align__(256) bf16 g_a1h[(size_t)E_ * B_ * H_];
__device__ __align__(256) bf16 g_a1l[(size_t)E_ * B_ * H_];
__device__ __align__(256) bf16 g_a2h[(size_t)E_ * B_ * H_];
__device__ __align__(256) bf16 g_a2l[(size_t)E_ * B_ * H_];
__device__ __align__(256) bf16 g_lth[(size_t)E_ * B_ * L_];
__device__ __align__(256) bf16 g_ltl[(size_t)E_ * B_ * L_];
__device__ float g_err[E_ * B_];
#define MAXBLK 40
#define MAXROW 5120
__device__ int g_cnt[E_], g_off[E_], g_cur[E_], g_nblk;
__device__ int g_blkexp[MAXBLK];
__device__ int g_rowidx[MAXROW];
__device__ int g_idxb[B_];

__device__ __forceinline__ const bf16* devHi(int s) {
    switch (s) { case 0: return g_xhi; case 1: return g_a1h; case 2: return g_a2h; default: return g_lth; }
}
__device__ __forceinline__ const bf16* devLo(int s) {
    switch (s) { case 0: return g_xlo; case 1: return g_a1l; case 2: return g_a2l; default: return g_ltl; }
}
__device__ __forceinline__ bf16* devHiW(int s) {
    switch (s) { case 1: return g_a1h; case 2: return g_a2h; default: return g_lth; }
}
__device__ __forceinline__ bf16* devLoW(int s) {
    switch (s) { case 1: return g_a1l; case 2: return g_a2l; default: return g_ltl; }
}

// ---------------- PTX helpers ----------------------------------------------
__device__ __forceinline__ uint32_t smem_u32(const void* p) {
    uint32_t a;
    asm("{ .reg .u64 t; cvta.to.shared.u64 t, %1; cvt.u32.u64 %0, t; }" : "=r"(a) : "l"(p));
    return a;
}
__device__ __forceinline__ void cpa16(uint32_t d, const void* s) {
    asm volatile("cp.async.cg.shared.global [%0], [%1], 16;" :: "r"(d), "l"(s));
}
#define LDSM4(r, addr) \
    asm volatile("ldmatrix.sync.aligned.m8n8.x4.shared.b16 {%0,%1,%2,%3}, [%4];" \
        : "=r"((r)[0]), "=r"((r)[1]), "=r"((r)[2]), "=r"((r)[3]) : "r"(addr))
#define MMA16816(d, a, b) \
    asm volatile("mma.sync.aligned.m16n8k16.row.col.f32.bf16.bf16.f32 " \
        "{%0,%1,%2,%3},{%4,%5,%6,%7},{%8,%9},{%0,%1,%2,%3};" \
        : "+f"((d)[0]), "+f"((d)[1]), "+f"((d)[2]), "+f"((d)[3]) \
        : "r"((a)[0]), "r"((a)[1]), "r"((a)[2]), "r"((a)[3]), "r"((b)[0]), "r"((b)[1]))

#define TPITCH 80
#define TILE_B (128 * TPITCH)
#define STG_B  (4 * TILE_B)
#define DSMEM  (2 * STG_B)          // 2-stage, 80 KB -> 2 CTAs/SM

// ---------------- bf16x3 GEMM, 4 warps, warp tile 64x64, 2-stage ------------
__global__ void __launch_bounds__(128)
gemm_k(int aSel, long long aStrE, int K, unsigned long long wOff,
       const float* __restrict__ bias, int biasStrE, int Nreal, int relu,
       int mode, float* __restrict__ fpOut, long long fpStrE, int fpLd,
       int oSel, long long oStrE, int oLd,
       int sparse, int gatherA, const float* __restrict__ xin)
{
    extern __shared__ char dsm[];
    int e;
    if (sparse) { if ((int)blockIdx.y >= g_nblk) return; e = g_blkexp[blockIdx.y]; }
    else e = blockIdx.z;
    const int tid = threadIdx.x, wid = tid >> 5, lane = tid & 31;
    const int m0 = blockIdx.y * 128, n0 = blockIdx.x * 128;
    const int warp_m = (wid >> 1) * 64, warp_n = (wid & 1) * 64;
    const uint32_t sb = smem_u32(dsm);
    const int nch = K >> 5;
    const size_t wStrE = (size_t)gridDim.x * 128 * K;

    const bf16* Ah = devHi(aSel) + (size_t)e * aStrE;
    const bf16* Al = devLo(aSel) + (size_t)e * aStrE;
    const bf16* Wh = g_whi + wOff + (size_t)e * wStrE + (size_t)n0 * K;
    const bf16* Wl = g_wlo + wOff + (size_t)e * wStrE + (size_t)n0 * K;

    size_t offA[4]; int rW[4], cC[4];
#pragma unroll
    for (int i = 0; i < 4; i++) {
        int c = i * 128 + tid, r = c >> 2;
        cC[i] = c & 3; rW[i] = r;
        int gr;
        if (gatherA) { gr = g_rowidx[m0 + r]; if (gr < 0) gr = 0; }
        else gr = m0 + r;
        offA[i] = (size_t)gr * K;
    }
    auto load_stage = [&](int stage, int j) {
        const uint32_t st = sb + stage * STG_B;
        const size_t kt = (size_t)j * 32;
#pragma unroll
        for (int i = 0; i < 4; i++) {
            const uint32_t dd = (uint32_t)(rW[i] * TPITCH + cC[i] * 16);
            const size_t so = kt + cC[i] * 8;
            cpa16(st + dd,              Ah + offA[i] + so);
            cpa16(st + TILE_B + dd,     Al + offA[i] + so);
            cpa16(st + 2 * TILE_B + dd, Wh + (size_t)rW[i] * K + so);
            cpa16(st + 3 * TILE_B + dd, Wl + (size_t)rW[i] * K + so);
        }
        asm volatile("cp.async.commit_group;" ::: "memory");
    };

    const int a_row = warp_m + ((lane >> 3) & 1) * 8 + (lane & 7);
    const int a_kh  = (lane >> 4) * 8;
    const int b_row = warp_n + (lane >> 4) * 8 + (lane & 7);
    const int b_kh  = ((lane >> 3) & 1) * 8;

    float acc[4][8][4];
#pragma unroll
    for (int i = 0; i < 4; i++)
#pragma unroll
        for (int j = 0; j < 8; j++)
#pragma unroll
            for (int k = 0; k < 4; k++) acc[i][j][k] = 0.f;

    load_stage(0, 0);
    for (int j = 0; j < nch; j++) {
        const int s = j & 1;
        if (j + 1 < nch) {
            load_stage(1 - s, j + 1);
            asm volatile("cp.async.wait_group 1;" ::: "memory");
        } else {
            asm volatile("cp.async.wait_group 0;" ::: "memory");
        }
        __syncthreads();
        const uint32_t st = sb + s * STG_B;
#pragma unroll
        for (int ks = 0; ks < 32; ks += 16) {
            uint32_t ah[4][4], al[4][4];
#pragma unroll
            for (int mt = 0; mt < 4; mt++) {
                const uint32_t off = (uint32_t)((a_row + mt * 16) * TPITCH + (ks + a_kh) * 2);
                LDSM4(ah[mt], st + off);
                LDSM4(al[mt], st + TILE_B + off);
            }
#pragma unroll
            for (int np = 0; np < 4; np++) {
                const uint32_t off = (uint32_t)((b_row + np * 16) * TPITCH + (ks + b_kh) * 2);
                uint32_t rh[4], rl[4];
                LDSM4(rh, st + 2 * TILE_B + off);
                LDSM4(rl, st + 3 * TILE_B + off);
                uint32_t bh0[2] = {rh[0], rh[1]}, bh1[2] = {rh[2], rh[3]};
                uint32_t bl0[2] = {rl[0], rl[1]}, bl1[2] = {rl[2], rl[3]};
                // product-major order: each acc re-touched at distance 8 MMAs
#pragma unroll
                for (int mt = 0; mt < 4; mt++) {
                    MMA16816(acc[mt][2 * np],     ah[mt], bh0);
                    MMA16816(acc[mt][2 * np + 1], ah[mt], bh1);
                }
#pragma unroll
                for (int mt = 0; mt < 4; mt++) {
                    MMA16816(acc[mt][2 * np],     al[mt], bh0);
                    MMA16816(acc[mt][2 * np + 1], al[mt], bh1);
                }
#pragma unroll
                for (int mt = 0; mt < 4; mt++) {
                    MMA16816(acc[mt][2 * np],     ah[mt], bl0);
                    MMA16816(acc[mt][2 * np + 1], ah[mt], bl1);
                }
            }
        }
        __syncthreads();
    }

    // ---------------- epilogue ----------------
    const int q = lane >> 2, l = lane & 3;
    float bv[8][2];
#pragma unroll
    for (int nt = 0; nt < 8; nt++) {
        int col = n0 + warp_n + nt * 8 + l * 2;
        bv[nt][0] = (col < Nreal)     ? bias[(size_t)e * biasStrE + col]     : 0.f;
        bv[nt][1] = (col + 1 < Nreal) ? bias[(size_t)e * biasStrE + col + 1] : 0.f;
    }
#pragma unroll
    for (int mt = 0; mt < 4; mt++) {
#pragma unroll
        for (int rh2 = 0; rh2 < 2; rh2++) {
            const int row = m0 + warp_m + mt * 16 + q + rh2 * 8;
            int brow = row;
            if (mode == 3) { brow = g_rowidx[row]; if (brow < 0) continue; }
            float esum = 0.f;
#pragma unroll
            for (int nt = 0; nt < 8; nt++) {
                const int col = n0 + warp_n + nt * 8 + l * 2;
                float v0 = acc[mt][nt][rh2 * 2]     + bv[nt][0];
                float v1 = acc[mt][nt][rh2 * 2 + 1] + bv[nt][1];
                if (relu) { v0 = fmaxf(v0, 0.f); v1 = fmaxf(v1, 0.f); }
                if (mode == 0) {
                    bf16 h0 = __float2bfloat16(v0), h1 = __float2bfloat16(v1);
                    bf16 l0 = __float2bfloat16(v0 - __bfloat162float(h0));
                    bf16 l1 = __float2bfloat16(v1 - __bfloat162float(h1));
                    bf16* oh = devHiW(oSel) + (size_t)e * oStrE + (size_t)row * oLd + col;
                    bf16* ol = devLoW(oSel) + (size_t)e * oStrE + (size_t)row * oLd + col;
                    *(uint32_t*)oh = ((uint32_t)__bfloat16_as_ushort(h1) << 16) | __bfloat16_as_ushort(h0);
                    *(uint32_t*)ol = ((uint32_t)__bfloat16_as_ushort(l1) << 16) | __bfloat16_as_ushort(l0);
                } else if (mode == 1) {
                    float* op = fpOut + (size_t)e * fpStrE + (size_t)row * fpLd;
                    op[col]     = v0;
                    op[col + 1] = v1;
                    const float x0 = xin[(size_t)row * fpLd + col];
                    const float x1 = xin[(size_t)row * fpLd + col + 1];
                    esum += fabsf(v0 - x0) + fabsf(v1 - x1);
                } else {
                    float* op = fpOut + (size_t)brow * fpLd;
                    if (col < Nreal)     op[col]     = v0;
                    if (col + 1 < Nreal) op[col + 1] = v1;
                }
            }
            if (mode == 1) {
                esum += __shfl_xor_sync(0xffffffffu, esum, 1);
                esum += __shfl_xor_sync(0xffffffffu, esum, 2);
                if (l == 0) atomicAdd(&g_err[e * B_ + row], esum);
            }
        }
    }
}

// ---------------- prep -----------------------------------------------------
__global__ void prep_x(const float* __restrict__ x) {
    size_t i = (size_t)blockIdx.x * blockDim.x + threadIdx.x;
    if (i < (size_t)B_ * D_) {
        float v = x[i];
        bf16 h = __float2bfloat16(v);
        g_xhi[i] = h;
        g_xlo[i] = __float2bfloat16(v - __bfloat162float(h));
    }
    if (i < E_ * B_) g_err[i] = 0.f;
}

// fused weight prep: all 9 layers in one launch. blockIdx.x selects (layer, tile).
struct WDesc { const float* W; int K, N, Npad; unsigned long long off; int blk0; };
__global__ void prep_w_all(WDesc d0, WDesc d1, WDesc d2, WDesc d3, WDesc d4,
                           WDesc d5, WDesc d6, WDesc d7, WDesc d8, int nTot)
{
    __shared__ float t[32][33];
    int gb = blockIdx.x;
    if (gb >= nTot) return;
    WDesc d;
    if      (gb >= d8.blk0) d = d8;
    else if (gb >= d7.blk0) d = d7;
    else if (gb >= d6.blk0) d = d6;
    else if (gb >= d5.blk0) d = d5;
    else if (gb >= d4.blk0) d = d4;
    else if (gb >= d3.blk0) d = d3;
    else if (gb >= d2.blk0) d = d2;
    else if (gb >= d1.blk0) d = d1;
    else                    d = d0;
    int lb = gb - d.blk0;
    const int tilesK = d.K / 32, tilesN = d.Npad / 32;
    const int e  = lb / (tilesK * tilesN);
    const int r2 = lb % (tilesK * tilesN);
    const int k0 = (r2 % tilesK) * 32, n0 = (r2 / tilesK) * 32;

    const float* Wp = d.W + (size_t)e * d.K * d.N;
    for (int r = threadIdx.y; r < 32; r += 8) {
        int n = n0 + threadIdx.x;
        t[r][threadIdx.x] = (n < d.N) ? Wp[(size_t)(k0 + r) * d.N + n] : 0.f;
    }
    __syncthreads();
    bf16* oh = g_whi + d.off + (size_t)e * d.Npad * d.K;
    bf16* ol = g_wlo + d.off + (size_t)e * d.Npad * d.K;
    for (int r = threadIdx.y; r < 32; r += 8) {
        float v = t[threadIdx.x][r];
        bf16 h = __float2bfloat16(v);
        bf16 l = __float2bfloat16(v - __bfloat162float(h));
        size_t o = (size_t)(n0 + r) * d.K + k0 + threadIdx.x;
        oh[o] = h; ol[o] = l;
    }
}

// ---------------- routing --------------------------------------------------
__global__ void route_init() {
    if (threadIdx.x < E_) { g_cnt[threadIdx.x] = 0; g_cur[threadIdx.x] = 0; }
}
__global__ void route1(float* __restrict__ out_idx, float* __restrict__ out_minerr,
                       float* __restrict__ out_rel, float* __restrict__ out_mask) {
    const int b = blockIdx.x * blockDim.x + threadIdx.x;
    if (b >= B_) return;
    const float invD = 1.0f / (float)D_;
    float ev[E_];
#pragma unroll
    for (int e = 0; e < E_; e++) ev[e] = g_err[e * B_ + b] * invD;
    int idx = 0; float mn = ev[0];
#pragma unroll
    for (int e = 1; e < E_; e++) if (ev[e] < mn) { mn = ev[e]; idx = e; }
    float p[E_], s = 0.f;
#pragma unroll
    for (int e = 0; e < E_; e++) { p[e] = expf((mn - ev[e]) * 0.5f); s += p[e]; }
    const float inv_s = 1.0f / s;
#pragma unroll
    for (int e = 0; e < E_; e++) {
        out_rel [e * B_ + b] = p[e] * inv_s;
        out_mask[e * B_ + b] = (e == idx) ? 1.f : 0.f;
    }
    out_idx[b] = (float)idx; out_minerr[b] = mn;
    g_idxb[b] = idx;
    atomicAdd(&g_cnt[idx], 1);
}
__global__ void route2() {
    if (threadIdx.x == 0) {
        int off = 0, blk = 0;
        for (int e = 0; e < E_; e++) {
            g_off[e] = off;
            int nb = (g_cnt[e] + 127) / 128;
            for (int k = 0; k < nb; k++) g_blkexp[blk++] = e;
            off += nb * 128;
        }
        g_nblk = blk;
    }
    for (int i = threadIdx.x; i < MAXROW; i += blockDim.x) g_rowidx[i] = -1;
}
__global__ void route3() {
    const int b = blockIdx.x * blockDim.x + threadIdx.x;
    if (b >= B_) return;
    const int e = g_idxb[b];
    const int pos = atomicAdd(&g_cur[e], 1);
    g_rowidx[g_off[e] + pos] = b;
}

// ---------------- host -----------------------------------------------------
extern "C" void kernel_launch(void* const* d_in, const int* in_sizes, int n_in,
                              void* d_out, int out_size)
{
    const float* x      = (const float*)d_in[0];
    const float* enc_w0 = (const float*)d_in[1];  const float* enc_b0 = (const float*)d_in[2];
    const float* enc_w1 = (const float*)d_in[3];  const float* enc_b1 = (const float*)d_in[4];
    const float* enc_w2 = (const float*)d_in[5];  const float* enc_b2 = (const float*)d_in[6];
    const float* dec_w0 = (const float*)d_in[7];  const float* dec_b0 = (const float*)d_in[8];
    const float* dec_w1 = (const float*)d_in[9];  const float* dec_b1 = (const float*)d_in[10];
    const float* dec_w2 = (const float*)d_in[11]; const float* dec_b2 = (const float*)d_in[12];
    const float* exp_w0 = (const float*)d_in[13]; const float* exp_b0 = (const float*)d_in[14];
    const float* exp_w1 = (const float*)d_in[15]; const float* exp_b1 = (const float*)d_in[16];
    const float* exp_w2 = (const float*)d_in[17]; const float* exp_b2 = (const float*)d_in[18];

    float* out = (float*)d_out;
    const long long RECON_OFF  = (long long)B_ * C_;
    const long long IDX_OFF    = RECON_OFF + (long long)E_ * B_ * D_;
    const long long MINERR_OFF = IDX_OFF + B_;
    const long long REL_OFF    = MINERR_OFF + B_;
    const long long MASK_OFF   = REL_OFF + (long long)E_ * B_;

    cudaFuncSetAttribute(gemm_k, cudaFuncAttributeMaxDynamicSharedMemorySize, DSMEM);

    // fused weight prep descriptors
    WDesc wd[9] = {
        {enc_w0, 3072, 1024, 1024, 0ULL, 0},
        {enc_w1, 1024, 1024, 1024, 25165824ULL, 0},
        {enc_w2, 1024,  512,  512, 33554432ULL, 0},
        {dec_w0,  512, 1024, 1024, 37748736ULL, 0},
        {dec_w1, 1024, 1024, 1024, 41943040ULL, 0},
        {dec_w2, 1024, 3072, 3072, 50331648ULL, 0},
        {exp_w0,  512, 1024, 1024, 75497472ULL, 0},
        {exp_w1, 1024, 1024, 1024, 79691776ULL, 0},
        {exp_w2, 1024,  100,  128, 88080384ULL, 0},
    };
    int acc_blk = 0;
    for (int i = 0; i < 9; i++) {
        wd[i].blk0 = acc_blk;
        acc_blk += E_ * (wd[i].K / 32) * (wd[i].Npad / 32);
    }

    auto G = [&](int aSel, long long aStrE, int K, unsigned long long wOff,
                 const float* bias, int biasStrE, int Nreal, int relu,
                 int mode, float* fpOut, long long fpStrE, int fpLd,
                 int oSel, long long oStrE, int oLd, int Npad) {
        gemm_k<<<dim3(Npad / 128, B_ / 128, E_), 128, DSMEM>>>(
            aSel, aStrE, K, wOff, bias, biasStrE, Nreal, relu,
            mode, fpOut, fpStrE, fpLd, oSel, oStrE, oLd, 0, 0, x);
    };
    auto GS = [&](int aSel, long long aStrE, int K, unsigned long long wOff,
                  const float* bias, int biasStrE, int Nreal, int relu,
                  int mode, float* fpOut, int fpLd,
                  int oSel, int oLd, int Npad, int gatherA) {
        gemm_k<<<dim3(Npad / 128, MAXBLK, 1), 128, DSMEM>>>(
            aSel, aStrE, K, wOff, bias, biasStrE, Nreal, relu,
            mode, fpOut, 0, fpLd, oSel, 0, oLd, 1, gatherA, x);
    };

    const long long BH = (long long)B_ * H_, BL = (long long)B_ * L_;

    prep_x<<<(B_ * D_ + 255) / 256, 256>>>(x);                              // 1
    prep_w_all<<<acc_blk, dim3(32, 8)>>>(wd[0], wd[1], wd[2], wd[3], wd[4],
                                         wd[5], wd[6], wd[7], wd[8], acc_blk); // 2
    route_init<<<1, 32>>>();                                                // 3
    G(0, 0,  3072, 0ULL,        enc_b0, H_, 1024, 1, 0, nullptr, 0, 0, 1, BH, H_, 1024); // 4
    G(1, BH, 1024, 25165824ULL, enc_b1, H_, 1024, 1, 0, nullptr, 0, 0, 2, BH, H_, 1024); // 5 <- profiled
    G(2, BH, 1024, 33554432ULL, enc_b2, L_,  512, 0, 0, nullptr, 0, 0, 3, BL, L_,  512);
    G(3, BL,  512, 37748736ULL, dec_b0, H_, 1024, 1, 0, nullptr, 0, 0, 1, BH, H_, 1024);
    G(1, BH, 1024, 41943040ULL, dec_b1, H_, 1024, 1, 0, nullptr, 0, 0, 2, BH, H_, 1024);
    G(2, BH, 1024, 50331648ULL, dec_b2, D_, 3072, 0, 1, out + RECON_OFF, (long long)B_ * D_, D_, 0, 0, 0, 3072);
    route1<<<B_ / 256, 256>>>(out + IDX_OFF, out + MINERR_OFF, out + REL_OFF, out + MASK_OFF);
    route2<<<1, 256>>>();
    route3<<<B_ / 256, 256>>>();
    GS(3, BL,  512, 75497472ULL, exp_b0, H_, 1024, 1, 0, nullptr, 0, 1, H_, 1024, 1);
    GS(1, 0,  1024, 79691776ULL, exp_b1, H_, 1024, 1, 0, nullptr, 0, 2, H_, 1024, 0);
    GS(2, 0,  1024, 88080384ULL, exp_b2, C_,  100, 0, 3, out, C_, 0, 0, 128, 0);
}

// round 17
// speedup vs baseline: 1.1992x; 1.1992x over previous
#include <cuda_runtime.h>
#include <cuda_bf16.h>
#include <math.h>
#include <stdint.h>

#define E_ 8
#define B_ 4096
#define D_ 3072
#define H_ 1024
#define L_ 512
#define C_ 100
typedef __nv_bfloat16 bf16;

// ---------------- device scratch -------------------------------------------
#define WTOTAL 89128960ULL
__device__ __align__(256) bf16 g_whi[WTOTAL];
__device__ __align__(256) bf16 g_wlo[WTOTAL];
__device__ __align__(256) bf16 g_xhi[(size_t)B_ * D_];
__device__ __align__(256) bf16 g_xlo[(size_t)B_ * D_];
__device__ __align__(256) bf16 g_a1h[(size_t)E_ * B_ * H_];
__device__ __align__(256) bf16 g_a1l[(size_t)E_ * B_ * H_];
__device__ __align__(256) bf16 g_a2h[(size_t)E_ * B_ * H_];
__device__ __align__(256) bf16 g_a2l[(size_t)E_ * B_ * H_];
__device__ __align__(256) bf16 g_lth[(size_t)E_ * B_ * L_];
__device__ __align__(256) bf16 g_ltl[(size_t)E_ * B_ * L_];
__device__ float g_err[E_ * B_];
#define MAXBLK 40
#define MAXROW 5120
__device__ int g_cnt[E_], g_off[E_], g_cur[E_], g_nblk;
__device__ int g_blkexp[MAXBLK];
__device__ int g_rowidx[MAXROW];
__device__ int g_idxb[B_];

__device__ __forceinline__ const bf16* devHi(int s) {
    switch (s) { case 0: return g_xhi; case 1: return g_a1h; case 2: return g_a2h; default: return g_lth; }
}
__device__ __forceinline__ const bf16* devLo(int s) {
    switch (s) { case 0: return g_xlo; case 1: return g_a1l; case 2: return g_a2l; default: return g_ltl; }
}
__device__ __forceinline__ bf16* devHiW(int s) {
    switch (s) { case 1: return g_a1h; case 2: return g_a2h; default: return g_lth; }
}
__device__ __forceinline__ bf16* devLoW(int s) {
    switch (s) { case 1: return g_a1l; case 2: return g_a2l; default: return g_ltl; }
}

// ---------------- PTX helpers ----------------------------------------------
__device__ __forceinline__ uint32_t smem_u32(const void* p) {
    uint32_t a;
    asm("{ .reg .u64 t; cvta.to.shared.u64 t, %1; cvt.u32.u64 %0, t; }" : "=r"(a) : "l"(p));
    return a;
}
__device__ __forceinline__ void cpa16(uint32_t d, const void* s) {
    asm volatile("cp.async.cg.shared.global [%0], [%1], 16;" :: "r"(d), "l"(s));
}
#define LDSM4(r, addr) \
    asm volatile("ldmatrix.sync.aligned.m8n8.x4.shared.b16 {%0,%1,%2,%3}, [%4];" \
        : "=r"((r)[0]), "=r"((r)[1]), "=r"((r)[2]), "=r"((r)[3]) : "r"(addr))
#define MMA16816(d, a, b) \
    asm volatile("mma.sync.aligned.m16n8k16.row.col.f32.bf16.bf16.f32 " \
        "{%0,%1,%2,%3},{%4,%5,%6,%7},{%8,%9},{%0,%1,%2,%3};" \
        : "+f"((d)[0]), "+f"((d)[1]), "+f"((d)[2]), "+f"((d)[3]) \
        : "r"((a)[0]), "r"((a)[1]), "r"((a)[2]), "r"((a)[3]), "r"((b)[0]), "r"((b)[1]))

// swizzled tile: 128 rows x 64B (32 bf16), addr(r,c16) = r*64 + (c16 ^ ((r>>1)&3))*16
__device__ __forceinline__ uint32_t swz(int r, int c16) {
    return (uint32_t)(r * 64 + ((c16 ^ ((r >> 1) & 3)) << 4));
}

#define TILE_B 8192
#define STG_B  (4 * TILE_B)        // Ah, Al, Wh, Wl = 32 KB
#define NSTG   3
#define DSMEM  (NSTG * STG_B)      // 96 KB -> 2 CTAs/SM (192 KB of 228)

// ---------------- bf16x3 GEMM, 4 warps, warp tile 64x64, 3-stage ------------
__global__ void __launch_bounds__(128)
gemm_k(int aSel, long long aStrE, int K, unsigned long long wOff,
       const float* __restrict__ bias, int biasStrE, int Nreal, int relu,
       int mode, float* __restrict__ fpOut, long long fpStrE, int fpLd,
       int oSel, long long oStrE, int oLd,
       int sparse, int gatherA, const float* __restrict__ xin)
{
    extern __shared__ char dsm[];
    int e;
    if (sparse) { if ((int)blockIdx.y >= g_nblk) return; e = g_blkexp[blockIdx.y]; }
    else e = blockIdx.z;
    const int tid = threadIdx.x, wid = tid >> 5, lane = tid & 31;
    const int m0 = blockIdx.y * 128, n0 = blockIdx.x * 128;
    const int warp_m = (wid >> 1) * 64, warp_n = (wid & 1) * 64;
    const uint32_t sb = smem_u32(dsm);
    const int nch = K >> 5;
    const size_t wStrE = (size_t)gridDim.x * 128 * K;

    const bf16* Ah = devHi(aSel) + (size_t)e * aStrE;
    const bf16* Al = devLo(aSel) + (size_t)e * aStrE;
    const bf16* Wh = g_whi + wOff + (size_t)e * wStrE + (size_t)n0 * K;
    const bf16* Wl = g_wlo + wOff + (size_t)e * wStrE + (size_t)n0 * K;

    // per-thread 4 chunks per tile (128x32 bf16 = 8192 B = 512 16B-chunks)
    size_t offA[4]; int rW[4]; uint32_t dd[4]; int cE[4];
#pragma unroll
    for (int i = 0; i < 4; i++) {
        int c = i * 128 + tid, r = c >> 2, c16 = c & 3;
        rW[i] = r; dd[i] = swz(r, c16); cE[i] = c16 * 8;
        int gr;
        if (gatherA) { gr = g_rowidx[m0 + r]; if (gr < 0) gr = 0; }
        else gr = m0 + r;
        offA[i] = (size_t)gr * K;
    }
    auto load_stage = [&](int stage, int j) {
        const uint32_t st = sb + stage * STG_B;
        const size_t kt = (size_t)j * 32;
#pragma unroll
        for (int i = 0; i < 4; i++) {
            const size_t so = kt + cE[i];
            cpa16(st + dd[i],              Ah + offA[i] + so);
            cpa16(st + TILE_B + dd[i],     Al + offA[i] + so);
            cpa16(st + 2 * TILE_B + dd[i], Wh + (size_t)rW[i] * K + so);
            cpa16(st + 3 * TILE_B + dd[i], Wl + (size_t)rW[i] * K + so);
        }
        asm volatile("cp.async.commit_group;" ::: "memory");
    };

    const int a_row = warp_m + ((lane >> 3) & 1) * 8 + (lane & 7);
    const int a_kh  = (lane >> 4) * 8;
    const int b_row = warp_n + (lane >> 4) * 8 + (lane & 7);
    const int b_kh  = ((lane >> 3) & 1) * 8;

    float acc[4][8][4];
#pragma unroll
    for (int i = 0; i < 4; i++)
#pragma unroll
        for (int j = 0; j < 8; j++)
#pragma unroll
            for (int k = 0; k < 4; k++) acc[i][j][k] = 0.f;

    // 3-stage, prefetch depth 2, ONE barrier per chunk
    load_stage(0, 0);
    if (nch > 1) load_stage(1, 1);
    for (int j = 0; j < nch; j++) {
        if (j + 1 < nch) asm volatile("cp.async.wait_group 1;" ::: "memory");
        else             asm volatile("cp.async.wait_group 0;" ::: "memory");
        __syncthreads();
        if (j + 2 < nch) load_stage((j + 2) % NSTG, j + 2);  // stage of j-1, already consumed
        const uint32_t st = sb + (j % NSTG) * STG_B;
#pragma unroll
        for (int ks = 0; ks < 32; ks += 16) {
            uint32_t ah[4][4], al[4][4];
            const int c16a = (ks + a_kh) >> 3;
#pragma unroll
            for (int mt = 0; mt < 4; mt++) {
                const int r = a_row + mt * 16;
                const uint32_t off = swz(r, c16a);
                LDSM4(ah[mt], st + off);
                LDSM4(al[mt], st + TILE_B + off);
            }
            const int c16b = (ks + b_kh) >> 3;
#pragma unroll
            for (int np = 0; np < 4; np++) {
                const int rb = b_row + np * 16;
                const uint32_t off = swz(rb, c16b);
                uint32_t rh[4], rl[4];
                LDSM4(rh, st + 2 * TILE_B + off);
                LDSM4(rl, st + 3 * TILE_B + off);
                uint32_t bh0[2] = {rh[0], rh[1]}, bh1[2] = {rh[2], rh[3]};
                uint32_t bl0[2] = {rl[0], rl[1]}, bl1[2] = {rl[2], rl[3]};
#pragma unroll
                for (int mt = 0; mt < 4; mt++) {
                    MMA16816(acc[mt][2 * np],     ah[mt], bh0);
                    MMA16816(acc[mt][2 * np + 1], ah[mt], bh1);
                }
#pragma unroll
                for (int mt = 0; mt < 4; mt++) {
                    MMA16816(acc[mt][2 * np],     al[mt], bh0);
                    MMA16816(acc[mt][2 * np + 1], al[mt], bh1);
                }
#pragma unroll
                for (int mt = 0; mt < 4; mt++) {
                    MMA16816(acc[mt][2 * np],     ah[mt], bl0);
                    MMA16816(acc[mt][2 * np + 1], ah[mt], bl1);
                }
            }
        }
    }

    // ---------------- epilogue ----------------
    const int q = lane >> 2, l = lane & 3;
    float bv[8][2];
#pragma unroll
    for (int nt = 0; nt < 8; nt++) {
        int col = n0 + warp_n + nt * 8 + l * 2;
        bv[nt][0] = (col < Nreal)     ? bias[(size_t)e * biasStrE + col]     : 0.f;
        bv[nt][1] = (col + 1 < Nreal) ? bias[(size_t)e * biasStrE + col + 1] : 0.f;
    }
#pragma unroll
    for (int mt = 0; mt < 4; mt++) {
#pragma unroll
        for (int rh2 = 0; rh2 < 2; rh2++) {
            const int row = m0 + warp_m + mt * 16 + q + rh2 * 8;
            int brow = row;
            if (mode == 3) { brow = g_rowidx[row]; if (brow < 0) continue; }
            float esum = 0.f;
#pragma unroll
            for (int nt = 0; nt < 8; nt++) {
                const int col = n0 + warp_n + nt * 8 + l * 2;
                float v0 = acc[mt][nt][rh2 * 2]     + bv[nt][0];
                float v1 = acc[mt][nt][rh2 * 2 + 1] + bv[nt][1];
                if (relu) { v0 = fmaxf(v0, 0.f); v1 = fmaxf(v1, 0.f); }
                if (mode == 0) {
                    bf16 h0 = __float2bfloat16(v0), h1 = __float2bfloat16(v1);
                    bf16 l0 = __float2bfloat16(v0 - __bfloat162float(h0));
                    bf16 l1 = __float2bfloat16(v1 - __bfloat162float(h1));
                    bf16* oh = devHiW(oSel) + (size_t)e * oStrE + (size_t)row * oLd + col;
                    bf16* ol = devLoW(oSel) + (size_t)e * oStrE + (size_t)row * oLd + col;
                    *(uint32_t*)oh = ((uint32_t)__bfloat16_as_ushort(h1) << 16) | __bfloat16_as_ushort(h0);
                    *(uint32_t*)ol = ((uint32_t)__bfloat16_as_ushort(l1) << 16) | __bfloat16_as_ushort(l0);
                } else if (mode == 1) {
                    float* op = fpOut + (size_t)e * fpStrE + (size_t)row * fpLd;
                    op[col]     = v0;
                    op[col + 1] = v1;
                    const float x0 = xin[(size_t)row * fpLd + col];
                    const float x1 = xin[(size_t)row * fpLd + col + 1];
                    esum += fabsf(v0 - x0) + fabsf(v1 - x1);
                } else {
                    float* op = fpOut + (size_t)brow * fpLd;
                    if (col < Nreal)     op[col]     = v0;
                    if (col + 1 < Nreal) op[col + 1] = v1;
                }
            }
            if (mode == 1) {
                esum += __shfl_xor_sync(0xffffffffu, esum, 1);
                esum += __shfl_xor_sync(0xffffffffu, esum, 2);
                if (l == 0) atomicAdd(&g_err[e * B_ + row], esum);
            }
        }
    }
}

// ---------------- prep -----------------------------------------------------
__global__ void prep_x(const float* __restrict__ x) {
    size_t i = (size_t)blockIdx.x * blockDim.x + threadIdx.x;
    if (i < (size_t)B_ * D_) {
        float v = x[i];
        bf16 h = __float2bfloat16(v);
        g_xhi[i] = h;
        g_xlo[i] = __float2bfloat16(v - __bfloat162float(h));
    }
    if (i < E_ * B_) g_err[i] = 0.f;
}

struct WDesc { const float* W; int K, N, Npad; unsigned long long off; int blk0; };
__global__ void prep_w_all(WDesc d0, WDesc d1, WDesc d2, WDesc d3, WDesc d4,
                           WDesc d5, WDesc d6, WDesc d7, WDesc d8, int nTot)
{
    __shared__ float t[32][33];
    int gb = blockIdx.x;
    if (gb >= nTot) return;
    WDesc d;
    if      (gb >= d8.blk0) d = d8;
    else if (gb >= d7.blk0) d = d7;
    else if (gb >= d6.blk0) d = d6;
    else if (gb >= d5.blk0) d = d5;
    else if (gb >= d4.blk0) d = d4;
    else if (gb >= d3.blk0) d = d3;
    else if (gb >= d2.blk0) d = d2;
    else if (gb >= d1.blk0) d = d1;
    else                    d = d0;
    int lb = gb - d.blk0;
    const int tilesK = d.K / 32, tilesN = d.Npad / 32;
    const int e  = lb / (tilesK * tilesN);
    const int r2 = lb % (tilesK * tilesN);
    const int k0 = (r2 % tilesK) * 32, n0 = (r2 / tilesK) * 32;

    const float* Wp = d.W + (size_t)e * d.K * d.N;
    for (int r = threadIdx.y; r < 32; r += 8) {
        int n = n0 + threadIdx.x;
        t[r][threadIdx.x] = (n < d.N) ? Wp[(size_t)(k0 + r) * d.N + n] : 0.f;
    }
    __syncthreads();
    bf16* oh = g_whi + d.off + (size_t)e * d.Npad * d.K;
    bf16* ol = g_wlo + d.off + (size_t)e * d.Npad * d.K;
    for (int r = threadIdx.y; r < 32; r += 8) {
        float v = t[threadIdx.x][r];
        bf16 h = __float2bfloat16(v);
        bf16 l = __float2bfloat16(v - __bfloat162float(h));
        size_t o = (size_t)(n0 + r) * d.K + k0 + threadIdx.x;
        oh[o] = h; ol[o] = l;
    }
}

// ---------------- routing --------------------------------------------------
__global__ void route_init() {
    if (threadIdx.x < E_) { g_cnt[threadIdx.x] = 0; g_cur[threadIdx.x] = 0; }
}
__global__ void route1(float* __restrict__ out_idx, float* __restrict__ out_minerr,
                       float* __restrict__ out_rel, float* __restrict__ out_mask) {
    const int b = blockIdx.x * blockDim.x + threadIdx.x;
    if (b >= B_) return;
    const float invD = 1.0f / (float)D_;
    float ev[E_];
#pragma unroll
    for (int e = 0; e < E_; e++) ev[e] = g_err[e * B_ + b] * invD;
    int idx = 0; float mn = ev[0];
#pragma unroll
    for (int e = 1; e < E_; e++) if (ev[e] < mn) { mn = ev[e]; idx = e; }
    float p[E_], s = 0.f;
#pragma unroll
    for (int e = 0; e < E_; e++) { p[e] = expf((mn - ev[e]) * 0.5f); s += p[e]; }
    const float inv_s = 1.0f / s;
#pragma unroll
    for (int e = 0; e < E_; e++) {
        out_rel [e * B_ + b] = p[e] * inv_s;
        out_mask[e * B_ + b] = (e == idx) ? 1.f : 0.f;
    }
    out_idx[b] = (float)idx; out_minerr[b] = mn;
    g_idxb[b] = idx;
    atomicAdd(&g_cnt[idx], 1);
}
__global__ void route2() {
    if (threadIdx.x == 0) {
        int off = 0, blk = 0;
        for (int e = 0; e < E_; e++) {
            g_off[e] = off;
            int nb = (g_cnt[e] + 127) / 128;
            for (int k = 0; k < nb; k++) g_blkexp[blk++] = e;
            off += nb * 128;
        }
        g_nblk = blk;
    }
    for (int i = threadIdx.x; i < MAXROW; i += blockDim.x) g_rowidx[i] = -1;
}
__global__ void route3() {
    const int b = blockIdx.x * blockDim.x + threadIdx.x;
    if (b >= B_) return;
    const int e = g_idxb[b];
    const int pos = atomicAdd(&g_cur[e], 1);
    g_rowidx[g_off[e] + pos] = b;
}

// ---------------- host -----------------------------------------------------
extern "C" void kernel_launch(void* const* d_in, const int* in_sizes, int n_in,
                              void* d_out, int out_size)
{
    const float* x      = (const float*)d_in[0];
    const float* enc_w0 = (const float*)d_in[1];  const float* enc_b0 = (const float*)d_in[2];
    const float* enc_w1 = (const float*)d_in[3];  const float* enc_b1 = (const float*)d_in[4];
    const float* enc_w2 = (const float*)d_in[5];  const float* enc_b2 = (const float*)d_in[6];
    const float* dec_w0 = (const float*)d_in[7];  const float* dec_b0 = (const float*)d_in[8];
    const float* dec_w1 = (const float*)d_in[9];  const float* dec_b1 = (const float*)d_in[10];
    const float* dec_w2 = (const float*)d_in[11]; const float* dec_b2 = (const float*)d_in[12];
    const float* exp_w0 = (const float*)d_in[13]; const float* exp_b0 = (const float*)d_in[14];
    const float* exp_w1 = (const float*)d_in[15]; const float* exp_b1 = (const float*)d_in[16];
    const float* exp_w2 = (const float*)d_in[17]; const float* exp_b2 = (const float*)d_in[18];

    float* out = (float*)d_out;
    const long long RECON_OFF  = (long long)B_ * C_;
    const long long IDX_OFF    = RECON_OFF + (long long)E_ * B_ * D_;
    const long long MINERR_OFF = IDX_OFF + B_;
    const long long REL_OFF    = MINERR_OFF + B_;
    const long long MASK_OFF   = REL_OFF + (long long)E_ * B_;

    cudaFuncSetAttribute(gemm_k, cudaFuncAttributeMaxDynamicSharedMemorySize, DSMEM);

    WDesc wd[9] = {
        {enc_w0, 3072, 1024, 1024, 0ULL, 0},
        {enc_w1, 1024, 1024, 1024, 25165824ULL, 0},
        {enc_w2, 1024,  512,  512, 33554432ULL, 0},
        {dec_w0,  512, 1024, 1024, 37748736ULL, 0},
        {dec_w1, 1024, 1024, 1024, 41943040ULL, 0},
        {dec_w2, 1024, 3072, 3072, 50331648ULL, 0},
        {exp_w0,  512, 1024, 1024, 75497472ULL, 0},
        {exp_w1, 1024, 1024, 1024, 79691776ULL, 0},
        {exp_w2, 1024,  100,  128, 88080384ULL, 0},
    };
    int acc_blk = 0;
    for (int i = 0; i < 9; i++) {
        wd[i].blk0 = acc_blk;
        acc_blk += E_ * (wd[i].K / 32) * (wd[i].Npad / 32);
    }

    auto G = [&](int aSel, long long aStrE, int K, unsigned long long wOff,
                 const float* bias, int biasStrE, int Nreal, int relu,
                 int mode, float* fpOut, long long fpStrE, int fpLd,
                 int oSel, long long oStrE, int oLd, int Npad) {
        gemm_k<<<dim3(Npad / 128, B_ / 128, E_), 128, DSMEM>>>(
            aSel, aStrE, K, wOff, bias, biasStrE, Nreal, relu,
            mode, fpOut, fpStrE, fpLd, oSel, oStrE, oLd, 0, 0, x);
    };
    auto GS = [&](int aSel, long long aStrE, int K, unsigned long long wOff,
                  const float* bias, int biasStrE, int Nreal, int relu,
                  int mode, float* fpOut, int fpLd,
                  int oSel, int oLd, int Npad, int gatherA) {
        gemm_k<<<dim3(Npad / 128, MAXBLK, 1), 128, DSMEM>>>(
            aSel, aStrE, K, wOff, bias, biasStrE, Nreal, relu,
            mode, fpOut, 0, fpLd, oSel, 0, oLd, 1, gatherA, x);
    };

    const long long BH = (long long)B_ * H_, BL = (long long)B_ * L_;

    prep_x<<<(B_ * D_ + 255) / 256, 256>>>(x);                              // 1
    prep_w_all<<<acc_blk, dim3(32, 8)>>>(wd[0], wd[1], wd[2], wd[3], wd[4],
                                         wd[5], wd[6], wd[7], wd[8], acc_blk); // 2
    route_init<<<1, 32>>>();                                                // 3
    G(0, 0,  3072, 0ULL,        enc_b0, H_, 1024, 1, 0, nullptr, 0, 0, 1, BH, H_, 1024); // 4
    G(1, BH, 1024, 25165824ULL, enc_b1, H_, 1024, 1, 0, nullptr, 0, 0, 2, BH, H_, 1024); // 5 <- profiled
    G(2, BH, 1024, 33554432ULL, enc_b2, L_,  512, 0, 0, nullptr, 0, 0, 3, BL, L_,  512);
    G(3, BL,  512, 37748736ULL, dec_b0, H_, 1024, 1, 0, nullptr, 0, 0, 1, BH, H_, 1024);
    G(1, BH, 1024, 41943040ULL, dec_b1, H_, 1024, 1, 0, nullptr, 0, 0, 2, BH, H_, 1024);
    G(2, BH, 1024, 50331648ULL, dec_b2, D_, 3072, 0, 1, out + RECON_OFF, (long long)B_ * D_, D_, 0, 0, 0, 3072);
    route1<<<B_ / 256, 256>>>(out + IDX_OFF, out + MINERR_OFF, out + REL_OFF, out + MASK_OFF);
    route2<<<1, 256>>>();
    route3<<<B_ / 256, 256>>>();
    GS(3, BL,  512, 75497472ULL, exp_b0, H_, 1024, 1, 0, nullptr, 0, 1, H_, 1024, 1);
    GS(1, 0,  1024, 79691776ULL, exp_b1, H_, 1024, 1, 0, nullptr, 0, 2, H_, 1024, 0);
    GS(2, 0,  1024, 88080384ULL, exp_b2, C_,  100, 0, 3, out, C_, 0, 0, 128, 0);
}